// round 2
// baseline (speedup 1.0000x reference)
#include <cuda_runtime.h>
#include <math.h>
#include <stdint.h>

#define NUM_SCALES 16
#define MAXP 524288u
#define HMASK (MAXP - 1u)
#define TPB 128

struct Cfg {
    float rx[NUM_SCALES], ry[NUM_SCALES], rz[NUM_SCALES], rt[NUM_SCALES];
    unsigned s1[NUM_SCALES], s2[NUM_SCALES], s3[NUM_SCALES];
    unsigned dense[NUM_SCALES];
    unsigned off2[NUM_SCALES];   // level offset in float2 units (= offset_floats / 2)
};

__global__ __launch_bounds__(TPB) void henc_kernel(
    const float4* __restrict__ xyzt,
    const float2* __restrict__ tbl,
    float* __restrict__ out,
    Cfg cfg, int nq)
{
    __shared__ float sm[TPB * 33];   // pitch 33 -> conflict-free column writes
    const int tid = threadIdx.x;
    const int q = blockIdx.x * TPB + tid;

    float4 p = (q < nq) ? xyzt[q] : make_float4(0.f, 0.f, 0.f, 0.f);

#pragma unroll 1
    for (int s = 0; s < NUM_SCALES; ++s) {
        // grid-space position (exact same fp32 ops as reference)
        float px = p.x * cfg.rx[s];
        float py = p.y * cfg.ry[s];
        float pz = p.z * cfg.rz[s];
        float pt = p.w * cfg.rt[s];
        float gx = floorf(px), gy = floorf(py), gz = floorf(pz), gt = floorf(pt);
        float fx = px - gx, fy = py - gy, fz = pz - gz, ft = pt - gt;
        unsigned ix = (unsigned)(int)gx, iy = (unsigned)(int)gy;
        unsigned iz = (unsigned)(int)gz, it = (unsigned)(int)gt;

        unsigned idx[16];
        if (cfg.dense[s]) {
            // dense linear index; reference's % size is the identity here
            unsigned t1 = cfg.s1[s], t2 = cfg.s2[s], t3 = cfg.s3[s];
            unsigned b0 = ix + iy * t1 + iz * t2 + it * t3;
#pragma unroll
            for (int c = 0; c < 16; ++c)
                idx[c] = b0 + (unsigned)(c & 1)
                            + (unsigned)((c >> 1) & 1) * t1
                            + (unsigned)((c >> 2) & 1) * t2
                            + (unsigned)((c >> 3) & 1) * t3;
        } else {
            // xor hash; size == 2^19 exactly -> mask
            unsigned hy0 = iy * 2654435761u, hy1 = (iy + 1u) * 2654435761u;
            unsigned hz0 = iz * 805459861u,  hz1 = (iz + 1u) * 805459861u;
            unsigned ht0 = it * 3674653429u, ht1 = (it + 1u) * 3674653429u;
#pragma unroll
            for (int c = 0; c < 16; ++c) {
                unsigned h = (ix + (unsigned)(c & 1))
                           ^ (((c >> 1) & 1) ? hy1 : hy0)
                           ^ (((c >> 2) & 1) ? hz1 : hz0)
                           ^ (((c >> 3) & 1) ? ht1 : ht0);
                idx[c] = h & HMASK;
            }
        }

        // issue all 16 independent 8B gathers (MLP = 16 LDG.64 per level)
        const float2* base = tbl + cfg.off2[s];
        float2 f[16];
#pragma unroll
        for (int c = 0; c < 16; ++c) f[c] = __ldg(base + idx[c]);

        // 4D multilinear weights via outer product
        float wx0 = 1.f - fx, wy0 = 1.f - fy, wz0 = 1.f - fz, wt0 = 1.f - ft;
        float wxy[4] = {wx0 * wy0, fx * wy0, wx0 * fy, fx * fy};
        float wzt[4] = {wz0 * wt0, fz * wt0, wz0 * ft, fz * ft};

        float o0 = 0.f, o1 = 0.f;
#pragma unroll
        for (int c = 0; c < 16; ++c) {
            float w = wxy[c & 3] * wzt[c >> 2];
            o0 = fmaf(w, f[c].x, o0);
            o1 = fmaf(w, f[c].y, o1);
        }

        sm[tid * 33 + 2 * s]     = o0;
        sm[tid * 33 + 2 * s + 1] = o1;
    }

    __syncthreads();

    // coalesced tile store: block's rows are contiguous in gmem
    int blockbase = blockIdx.x * (TPB * 32);
    int lim = nq * 32;
#pragma unroll
    for (int k = 0; k < 32; ++k) {
        int i = tid + k * TPB;
        int g = blockbase + i;
        if (g < lim) out[g] = sm[(i >> 5) * 33 + (i & 31)];
    }
}

extern "C" void kernel_launch(void* const* d_in, const int* in_sizes, int n_in,
                              void* d_out, int out_size)
{
    (void)n_in; (void)out_size;

    // Rebuild the reference's build_config() with the same float64 libm math.
    Cfg cfg;
    const double minr[4] = {16.0, 16.0, 16.0, 16.0};
    const double maxr[4] = {256.0, 256.0, 256.0, 128.0};
    double b[4];
    for (int d = 0; d < 4; ++d)
        b[d] = exp((log(maxr[d]) - log(minr[d])) / (double)(NUM_SCALES - 1));

    unsigned long long totalp = 0;  // cumulative params (= offset_floats/2)
    for (int s = 0; s < NUM_SCALES; ++s) {
        long long res[4];
        for (int d = 0; d < 4; ++d)
            res[d] = (long long)ceil(minr[d] * pow(b[d], (double)s));
        long long raw = (res[0] + 1) * (res[1] + 1) * (res[2] + 1) * (res[3] + 1);
        long long pp = (raw % 8 == 0) ? raw : ((raw + 7) / 8) * 8;
        if (pp > (long long)MAXP) pp = (long long)MAXP;

        cfg.dense[s] = (raw <= pp) ? 1u : 0u;
        cfg.rx[s] = (float)res[0];
        cfg.ry[s] = (float)res[1];
        cfg.rz[s] = (float)res[2];
        cfg.rt[s] = (float)res[3];
        cfg.s1[s] = (unsigned)(res[0] + 1);
        cfg.s2[s] = (unsigned)((res[0] + 1) * (res[1] + 1));
        cfg.s3[s] = (unsigned)((res[0] + 1) * (res[1] + 1) * (res[2] + 1));
        cfg.off2[s] = (unsigned)totalp;
        totalp += (unsigned long long)pp;
    }

    int nq = in_sizes[0] / 4;
    const float4* xyzt = (const float4*)d_in[0];
    const float2* tbl  = (const float2*)d_in[1];
    float* out = (float*)d_out;

    int blocks = (nq + TPB - 1) / TPB;
    henc_kernel<<<blocks, TPB>>>(xyzt, tbl, out, cfg, nq);
}

// round 5
// speedup vs baseline: 2.2095x; 2.2095x over previous
#include <cuda_runtime.h>
#include <math.h>
#include <stdint.h>

#define NUM_SCALES 16
#define MAXP 524288u
#define HMASK (MAXP - 1u)
#define TPB 128

struct Cfg {
    float rx[NUM_SCALES], ry[NUM_SCALES], rz[NUM_SCALES], rt[NUM_SCALES];
    unsigned s1[NUM_SCALES], s2[NUM_SCALES], s3[NUM_SCALES];
    unsigned dense[NUM_SCALES];
    unsigned off2[NUM_SCALES];   // level offset in float2 units
};

// Compute one level's 16 corner gathers (issued back-to-back for MLP=16)
// plus the interpolation weight factors. No idx array: addresses are
// computed just-in-time so only the 16 float2 destinations stay live.
__device__ __forceinline__ void level_issue(
    const Cfg& cfg, int s, float4 p, const float2* __restrict__ tbl,
    float2* f, float* wxy, float* wzt)
{
    float px = p.x * cfg.rx[s];
    float py = p.y * cfg.ry[s];
    float pz = p.z * cfg.rz[s];
    float pt = p.w * cfg.rt[s];
    float gx = floorf(px), gy = floorf(py), gz = floorf(pz), gt = floorf(pt);
    float fx = px - gx, fy = py - gy, fz = pz - gz, ft = pt - gt;
    unsigned ix = (unsigned)(int)gx, iy = (unsigned)(int)gy;
    unsigned iz = (unsigned)(int)gz, it = (unsigned)(int)gt;

    const float2* __restrict__ base = tbl + cfg.off2[s];

    if (cfg.dense[s]) {
        // dense linear index; reference's % size is the identity here
        unsigned t1 = cfg.s1[s], t2 = cfg.s2[s], t3 = cfg.s3[s];
        unsigned b0 = iy * t1 + iz * t2 + it * t3;
        unsigned byzt[8];
#pragma unroll
        for (int j = 0; j < 8; ++j)
            byzt[j] = b0 + ((j & 1) ? t1 : 0u) + ((j & 2) ? t2 : 0u) + ((j & 4) ? t3 : 0u);
#pragma unroll
        for (int c = 0; c < 16; ++c)
            f[c] = __ldg(base + (ix + (unsigned)(c & 1) + byzt[c >> 1]));
    } else {
        // xor hash; size == 2^19 exactly -> mask
        unsigned hy0 = iy * 2654435761u, hy1 = (iy + 1u) * 2654435761u;
        unsigned hz0 = iz * 805459861u,  hz1 = (iz + 1u) * 805459861u;
        unsigned ht0 = it * 3674653429u, ht1 = (it + 1u) * 3674653429u;
        unsigned ryzt[8];
#pragma unroll
        for (int j = 0; j < 8; ++j)
            ryzt[j] = ((j & 1) ? hy1 : hy0) ^ ((j & 2) ? hz1 : hz0) ^ ((j & 4) ? ht1 : ht0);
#pragma unroll
        for (int c = 0; c < 16; ++c)
            f[c] = __ldg(base + (((ix + (unsigned)(c & 1)) ^ ryzt[c >> 1]) & HMASK));
    }

    float wx0 = 1.f - fx, wy0 = 1.f - fy, wz0 = 1.f - fz, wt0 = 1.f - ft;
    wxy[0] = wx0 * wy0; wxy[1] = fx * wy0; wxy[2] = wx0 * fy; wxy[3] = fx * fy;
    wzt[0] = wz0 * wt0; wzt[1] = fz * wt0; wzt[2] = wz0 * ft; wzt[3] = fz * ft;
}

__device__ __forceinline__ float2 level_consume(
    const float2* f, const float* wxy, const float* wzt)
{
    float o0 = 0.f, o1 = 0.f;
#pragma unroll
    for (int c = 0; c < 16; ++c) {
        float w = wxy[c & 3] * wzt[c >> 2];
        o0 = fmaf(w, f[c].x, o0);
        o1 = fmaf(w, f[c].y, o1);
    }
    return make_float2(o0, o1);
}

__global__ __launch_bounds__(TPB, 4) void henc_kernel(
    const float4* __restrict__ xyzt,
    const float2* __restrict__ tbl,
    float2* __restrict__ out2,
    Cfg cfg, int nq)
{
    __shared__ float2 sm2[TPB * 17];   // pitch 17 float2s -> conflict-free
    const int tid = threadIdx.x;
    const int q = blockIdx.x * TPB + tid;

    float4 p = (q < nq) ? xyzt[q] : make_float4(0.f, 0.f, 0.f, 0.f);

    float2 fA[16], fB[16];
    float wxyA[4], wztA[4], wxyB[4], wztB[4];

    // prologue: level 0 loads in flight before any consumption
    level_issue(cfg, 0, p, tbl, fA, wxyA, wztA);

#pragma unroll 1
    for (int s = 0; s < NUM_SCALES; s += 2) {
        // issue level s+1 while level s loads are landing
        level_issue(cfg, s + 1, p, tbl, fB, wxyB, wztB);
        sm2[tid * 17 + s] = level_consume(fA, wxyA, wztA);
        // issue level s+2 while level s+1 loads are landing
        if (s + 2 < NUM_SCALES)
            level_issue(cfg, s + 2, p, tbl, fA, wxyA, wztA);
        sm2[tid * 17 + s + 1] = level_consume(fB, wxyB, wztB);
    }

    __syncthreads();

    // coalesced float2 tile store: block's rows are contiguous in gmem
    int base2 = blockIdx.x * (TPB * 16);
    int lim2 = nq * 16;
#pragma unroll
    for (int k = 0; k < 16; ++k) {
        int i = tid + k * TPB;
        int g = base2 + i;
        if (g < lim2) out2[g] = sm2[(i >> 4) * 17 + (i & 15)];
    }
}

extern "C" void kernel_launch(void* const* d_in, const int* in_sizes, int n_in,
                              void* d_out, int out_size)
{
    (void)n_in; (void)out_size;

    // Rebuild the reference's build_config() with the same float64 libm math.
    Cfg cfg;
    const double minr[4] = {16.0, 16.0, 16.0, 16.0};
    const double maxr[4] = {256.0, 256.0, 256.0, 128.0};
    double b[4];
    for (int d = 0; d < 4; ++d)
        b[d] = exp((log(maxr[d]) - log(minr[d])) / (double)(NUM_SCALES - 1));

    unsigned long long totalp = 0;
    for (int s = 0; s < NUM_SCALES; ++s) {
        long long res[4];
        for (int d = 0; d < 4; ++d)
            res[d] = (long long)ceil(minr[d] * pow(b[d], (double)s));
        long long raw = (res[0] + 1) * (res[1] + 1) * (res[2] + 1) * (res[3] + 1);
        long long pp = (raw % 8 == 0) ? raw : ((raw + 7) / 8) * 8;
        if (pp > (long long)MAXP) pp = (long long)MAXP;

        cfg.dense[s] = (raw <= pp) ? 1u : 0u;
        cfg.rx[s] = (float)res[0];
        cfg.ry[s] = (float)res[1];
        cfg.rz[s] = (float)res[2];
        cfg.rt[s] = (float)res[3];
        cfg.s1[s] = (unsigned)(res[0] + 1);
        cfg.s2[s] = (unsigned)((res[0] + 1) * (res[1] + 1));
        cfg.s3[s] = (unsigned)((res[0] + 1) * (res[1] + 1) * (res[2] + 1));
        cfg.off2[s] = (unsigned)totalp;
        totalp += (unsigned long long)pp;
    }

    int nq = in_sizes[0] / 4;
    const float4* xyzt = (const float4*)d_in[0];
    const float2* tbl  = (const float2*)d_in[1];
    float2* out2 = (float2*)d_out;

    int blocks = (nq + TPB - 1) / TPB;
    henc_kernel<<<blocks, TPB>>>(xyzt, tbl, out2, cfg, nq);
}

// round 6
// speedup vs baseline: 2.5832x; 1.1691x over previous
#include <cuda_runtime.h>
#include <math.h>
#include <stdint.h>

#define NUM_SCALES 16
#define MAXP 524288u
#define HMASK (MAXP - 1u)
#define TPB 128

struct Cfg {
    float rx[NUM_SCALES], ry[NUM_SCALES], rz[NUM_SCALES], rt[NUM_SCALES];
    unsigned s1[NUM_SCALES], s2[NUM_SCALES], s3[NUM_SCALES];
    unsigned dense[NUM_SCALES];
    unsigned off2[NUM_SCALES];   // level offset in float2 units (16B-aligned: p % 8 == 0)
};

struct LvlBuf {
    float4 f4[8];     // aligned pair-words: entries {2m, 2m+1} containing corner 2j
    float2 fb[8];     // fallback load of corner 2j+1 when pair not adjacent
    unsigned selmask; // bit j: corner 2j sits in high half (a odd)
    unsigned adjmask; // bit j: pair adjacent -> corner 2j+1 is the other half of f4[j]
};

// Issue one level's gathers with maximum MLP:
// 8x LDG.128 (always) + 8x predicated LDG.64 (only non-adjacent lanes).
__device__ __forceinline__ void level_issue(
    const Cfg& cfg, int s, float4 p, const float2* __restrict__ tbl,
    LvlBuf& B, float* wxy, float* wzt)
{
    float px = p.x * cfg.rx[s];
    float py = p.y * cfg.ry[s];
    float pz = p.z * cfg.rz[s];
    float pt = p.w * cfg.rt[s];
    float gx = floorf(px), gy = floorf(py), gz = floorf(pz), gt = floorf(pt);
    float fx = px - gx, fy = py - gy, fz = pz - gz, ft = pt - gt;
    unsigned ix = (unsigned)(int)gx, iy = (unsigned)(int)gy;
    unsigned iz = (unsigned)(int)gz, it = (unsigned)(int)gt;

    const float2* __restrict__ base = tbl + cfg.off2[s];
    const float4* __restrict__ base4 = (const float4*)base;

    unsigned a[8], b[8];
    if (cfg.dense[s]) {
        unsigned t1 = cfg.s1[s], t2 = cfg.s2[s], t3 = cfg.s3[s];
        unsigned b0 = ix + iy * t1 + iz * t2 + it * t3;
#pragma unroll
        for (int j = 0; j < 8; ++j) {
            unsigned byzt = b0 + ((j & 1) ? t1 : 0u) + ((j & 2) ? t2 : 0u) + ((j & 4) ? t3 : 0u);
            a[j] = byzt;          // x = ix corner
            b[j] = byzt + 1u;     // x = ix+1 corner
        }
    } else {
        unsigned hy0 = iy * 2654435761u, hy1 = (iy + 1u) * 2654435761u;
        unsigned hz0 = iz * 805459861u,  hz1 = (iz + 1u) * 805459861u;
        unsigned ht0 = it * 3674653429u, ht1 = (it + 1u) * 3674653429u;
#pragma unroll
        for (int j = 0; j < 8; ++j) {
            unsigned r = ((j & 1) ? hy1 : hy0) ^ ((j & 2) ? hz1 : hz0) ^ ((j & 4) ? ht1 : ht0);
            a[j] = (ix ^ r) & HMASK;
            b[j] = ((ix + 1u) ^ r) & HMASK;
        }
    }

    unsigned selmask = 0u, adjmask = 0u;
#pragma unroll
    for (int j = 0; j < 8; ++j) {
        B.f4[j] = __ldg(base4 + (a[j] >> 1));
        selmask |= (a[j] & 1u) << j;
        adjmask |= ((a[j] ^ b[j]) == 1u ? 1u : 0u) << j;
    }
#pragma unroll
    for (int j = 0; j < 8; ++j) {
        if ((a[j] ^ b[j]) != 1u)
            B.fb[j] = __ldg(base + b[j]);   // predicated: only non-adjacent lanes
    }
    B.selmask = selmask;
    B.adjmask = adjmask;

    float wx0 = 1.f - fx, wy0 = 1.f - fy, wz0 = 1.f - fz, wt0 = 1.f - ft;
    wxy[0] = wx0 * wy0; wxy[1] = fx * wy0; wxy[2] = wx0 * fy; wxy[3] = fx * fy;
    wzt[0] = wz0 * wt0; wzt[1] = fz * wt0; wzt[2] = wz0 * ft; wzt[3] = fz * ft;
}

__device__ __forceinline__ float2 level_consume(
    const LvlBuf& B, const float* wxy, const float* wzt)
{
    float o0 = 0.f, o1 = 0.f;
#pragma unroll
    for (int j = 0; j < 8; ++j) {
        bool hi  = (B.selmask >> j) & 1u;
        bool adj = (B.adjmask >> j) & 1u;
        float4 q = B.f4[j];
        float c0x = hi ? q.z : q.x, c0y = hi ? q.w : q.y;       // corner 2j
        float c1x = hi ? q.x : q.z, c1y = hi ? q.y : q.w;       // other half
        if (!adj) { c1x = B.fb[j].x; c1y = B.fb[j].y; }         // corner 2j+1 fallback
        float wz = wzt[j >> 1];
        float w0 = wxy[(j & 1) * 2]     * wz;
        float w1 = wxy[(j & 1) * 2 + 1] * wz;
        o0 = fmaf(w0, c0x, o0); o1 = fmaf(w0, c0y, o1);
        o0 = fmaf(w1, c1x, o0); o1 = fmaf(w1, c1y, o1);
    }
    return make_float2(o0, o1);
}

__global__ __launch_bounds__(TPB, 3) void henc_kernel(
    const float4* __restrict__ xyzt,
    const float2* __restrict__ tbl,
    float2* __restrict__ out2,
    Cfg cfg, int nq)
{
    __shared__ float2 sm2[TPB * 17];   // pitch 17 float2s -> conflict-free
    const int tid = threadIdx.x;
    const int q = blockIdx.x * TPB + tid;

    float4 p = (q < nq) ? xyzt[q] : make_float4(0.f, 0.f, 0.f, 0.f);

    LvlBuf A, B;
    float wxyA[4], wztA[4], wxyB[4], wztB[4];

    // prologue: level 0 loads in flight before any consumption
    level_issue(cfg, 0, p, tbl, A, wxyA, wztA);

#pragma unroll 1
    for (int s = 0; s < NUM_SCALES; s += 2) {
        level_issue(cfg, s + 1, p, tbl, B, wxyB, wztB);
        sm2[tid * 17 + s] = level_consume(A, wxyA, wztA);
        if (s + 2 < NUM_SCALES)
            level_issue(cfg, s + 2, p, tbl, A, wxyA, wztA);
        sm2[tid * 17 + s + 1] = level_consume(B, wxyB, wztB);
    }

    __syncthreads();

    // coalesced float2 tile store: block's rows are contiguous in gmem
    int base2 = blockIdx.x * (TPB * 16);
    int lim2 = nq * 16;
#pragma unroll
    for (int k = 0; k < 16; ++k) {
        int i = tid + k * TPB;
        int g = base2 + i;
        if (g < lim2) out2[g] = sm2[(i >> 4) * 17 + (i & 15)];
    }
}

extern "C" void kernel_launch(void* const* d_in, const int* in_sizes, int n_in,
                              void* d_out, int out_size)
{
    (void)n_in; (void)out_size;

    // Rebuild the reference's build_config() with the same float64 libm math.
    Cfg cfg;
    const double minr[4] = {16.0, 16.0, 16.0, 16.0};
    const double maxr[4] = {256.0, 256.0, 256.0, 128.0};
    double b[4];
    for (int d = 0; d < 4; ++d)
        b[d] = exp((log(maxr[d]) - log(minr[d])) / (double)(NUM_SCALES - 1));

    unsigned long long totalp = 0;
    for (int s = 0; s < NUM_SCALES; ++s) {
        long long res[4];
        for (int d = 0; d < 4; ++d)
            res[d] = (long long)ceil(minr[d] * pow(b[d], (double)s));
        long long raw = (res[0] + 1) * (res[1] + 1) * (res[2] + 1) * (res[3] + 1);
        long long pp = (raw % 8 == 0) ? raw : ((raw + 7) / 8) * 8;
        if (pp > (long long)MAXP) pp = (long long)MAXP;

        cfg.dense[s] = (raw <= pp) ? 1u : 0u;
        cfg.rx[s] = (float)res[0];
        cfg.ry[s] = (float)res[1];
        cfg.rz[s] = (float)res[2];
        cfg.rt[s] = (float)res[3];
        cfg.s1[s] = (unsigned)(res[0] + 1);
        cfg.s2[s] = (unsigned)((res[0] + 1) * (res[1] + 1));
        cfg.s3[s] = (unsigned)((res[0] + 1) * (res[1] + 1) * (res[2] + 1));
        cfg.off2[s] = (unsigned)totalp;
        totalp += (unsigned long long)pp;
    }

    int nq = in_sizes[0] / 4;
    const float4* xyzt = (const float4*)d_in[0];
    const float2* tbl  = (const float2*)d_in[1];
    float2* out2 = (float2*)d_out;

    int blocks = (nq + TPB - 1) / TPB;
    henc_kernel<<<blocks, TPB>>>(xyzt, tbl, out2, cfg, nq);
}